// round 14
// baseline (speedup 1.0000x reference)
#include <cuda_runtime.h>
#include <cuda_fp16.h>
#include <cstdint>

#define B_  512
#define T_  1024
#define IN_ 128
#define NG_ 256
#define BT_ (B_ * T_)
#define MTILES 4096          // BT_/128 m-tiles per dir

// xg scratch: [dir][b*T+t][hh*4 + slot], slot: 0=i,1=g,2=f,3=o  (1 GiB)
__device__ float g_G[(size_t)2 * BT_ * NG_];

// ---------------- smem map (bytes) for gates_gemm ----------------
#define XSTRIDE 272
#define SM_XH   0
#define SM_WHI  (SM_XH + 128 * XSTRIDE)      //  34816
#define SM_BIAS (SM_WHI + 256 * XSTRIDE)     // 104448
#define SM_TOTAL (SM_BIAS + 1024)            // 105472

// ---------------- smem map (bytes) for lstm_rec ----------------
// W stage: 256 rows x 272 B; h: 2 bufs x 16 rows x 272 B;
// xg: 3 bufs x 16 rows x 1056 B (264-float padded rows).
#define R_W   0
#define R_H   69632
#define R_XG  (R_H + 2 * 16 * 272)           // 78336
#define R_TOT (R_XG + 3 * 16896)             // 129024

// ---------------- ptx helpers ----------------
__device__ __forceinline__ uint32_t smem_u32(const void* p) {
    return (uint32_t)__cvta_generic_to_shared(p);
}
__device__ __forceinline__ void ldsm4(uint32_t* r, uint32_t addr) {
    asm volatile("ldmatrix.sync.aligned.m8n8.x4.shared.b16 {%0,%1,%2,%3}, [%4];"
                 : "=r"(r[0]), "=r"(r[1]), "=r"(r[2]), "=r"(r[3]) : "r"(addr));
}
__device__ __forceinline__ void mma16816(float* c, const uint32_t* a,
                                         uint32_t b0, uint32_t b1) {
    asm volatile(
        "mma.sync.aligned.m16n8k16.row.col.f32.f16.f16.f32 "
        "{%0,%1,%2,%3}, {%4,%5,%6,%7}, {%8,%9}, {%0,%1,%2,%3};"
        : "+f"(c[0]), "+f"(c[1]), "+f"(c[2]), "+f"(c[3])
        : "r"(a[0]), "r"(a[1]), "r"(a[2]), "r"(a[3]), "r"(b0), "r"(b1));
}

// fp16x2 pack of two floats (lo half = a, hi half = b)
__device__ __forceinline__ uint32_t cvt2h(float a, float b) {
    __half2 h = __floats2half2_rn(a, b);
    return *reinterpret_cast<uint32_t*>(&h);
}

// ---------------- activations (MUFU tanh) ----------------
__device__ __forceinline__ float tanh_fast(float x) {
    float y;
    asm("tanh.approx.f32 %0, %1;" : "=f"(y) : "f"(x));
    return y;
}
__device__ __forceinline__ float sig_fast(float x) {
    return fmaf(tanh_fast(0.5f * x), 0.5f, 0.5f);
}

// ---------------- cp.async ----------------
__device__ __forceinline__ void cp_async16(uint32_t dst, const void* src) {
    asm volatile("cp.async.cg.shared.global [%0], [%1], 16;" :: "r"(dst), "l"(src));
}
__device__ __forceinline__ void cp_commit() {
    asm volatile("cp.async.commit_group;");
}
__device__ __forceinline__ void cp_wait1() {
    asm volatile("cp.async.wait_group 1;");
}

// =======================================================================
// Kernel 1: HMMA pure-fp16 GEMM (R13 winner, unchanged).
// D[128m,256p] = f16(x) @ f16(W)^T  (fp32 register accs).
// 148 CTAs x 512 thr (16 warps): warp tile 32m x 64n.
// =======================================================================
__global__ void __launch_bounds__(512, 1) gates_gemm(
    const float* __restrict__ x,
    const float* __restrict__ Wf, const float* __restrict__ bf,
    const float* __restrict__ Wb, const float* __restrict__ bb)
{
    extern __shared__ char sm[];
    const uint32_t smb = smem_u32(sm);

    const int tid  = threadIdx.x;
    const int wid  = tid >> 5;
    const int lane = tid & 31;
    const int dir  = blockIdx.x & 1;
    const int cpos = blockIdx.x >> 1;   // 0..73

    const float* W    = dir ? Wb : Wf;
    const float* bias = dir ? bb : bf;

    // ---- load + convert W to f16 at permuted row p (once) ----
    {
        const int j    = tid >> 1;          // 0..255
        const int half = tid & 1;           // k half
        const int g    = j >> 6;
        const int slot = (g == 0) ? 0 : (g == 1) ? 2 : (g == 2) ? 1 : 3;
        const int p    = ((j & 63) << 2) | slot;
        const float4* wr = (const float4*)(W + j * IN_ + half * 64);
        char* whi = sm + SM_WHI + p * XSTRIDE + half * 128;
#pragma unroll
        for (int q = 0; q < 16; q++) {
            float4 v = wr[q];
            *(uint2*)(whi + q * 8) = make_uint2(cvt2h(v.x, v.y), cvt2h(v.z, v.w));
        }
        if (half == 0) ((float*)(sm + SM_BIAS))[p] = bias[j];
    }

    const int msub  = (wid & 3) * 32;
    const int nsub0 = (wid >> 2) * 64;

    const uint32_t aoff = (uint32_t)(msub + (lane & 15)) * XSTRIDE + (lane >> 4) * 16;
    const uint32_t boff = (uint32_t)(nsub0 + (lane & 7) + ((lane >> 4) << 3)) * XSTRIDE
                          + ((lane >> 3) & 1) * 16;

    const int r0c = tid >> 5;
    const int lc  = tid & 31;

    for (int mt = cpos; mt < MTILES; mt += 74) {
        __syncthreads();

        {
            const float* srcb = x + (size_t)mt * 128 * IN_;
#pragma unroll
            for (int i = 0; i < 4; i++) {
                const int row0 = r0c + 32 * i;
                float4 v0 = *(const float4*)(srcb + (size_t)row0 * IN_ + lc * 4);
                float4 v1 = *(const float4*)(srcb + (size_t)(row0 + 16) * IN_ + lc * 4);
                *(uint2*)(sm + SM_XH + row0 * XSTRIDE + lc * 8) =
                    make_uint2(cvt2h(v0.x, v0.y), cvt2h(v0.z, v0.w));
                *(uint2*)(sm + SM_XH + (row0 + 16) * XSTRIDE + lc * 8) =
                    make_uint2(cvt2h(v1.x, v1.y), cvt2h(v1.z, v1.w));
            }
        }
        __syncthreads();

        float acc[2][8][4];
#pragma unroll
        for (int m2 = 0; m2 < 2; m2++)
#pragma unroll
            for (int j = 0; j < 8; j++)
#pragma unroll
                for (int q = 0; q < 4; q++) acc[m2][j][q] = 0.f;

        const uint32_t aH  = smb + SM_XH + aoff;
        const uint32_t bHi = smb + SM_WHI + boff;

#pragma unroll
        for (int k8 = 0; k8 < 8; k8++) {
            uint32_t ah0[4], ah1[4];
            ldsm4(ah0, aH + k8 * 32);
            ldsm4(ah1, aH + 16 * XSTRIDE + k8 * 32);
#pragma unroll
            for (int jp = 0; jp < 4; jp++) {
                uint32_t bh[4];
                ldsm4(bh, bHi + jp * (16 * XSTRIDE) + k8 * 32);
                mma16816(acc[0][2 * jp + 0], ah0, bh[0], bh[1]);
                mma16816(acc[0][2 * jp + 1], ah0, bh[2], bh[3]);
                mma16816(acc[1][2 * jp + 0], ah1, bh[0], bh[1]);
                mma16816(acc[1][2 * jp + 1], ah1, bh[2], bh[3]);
            }
        }

        {
            const int g  = lane >> 2;
            const int t2 = (lane & 3) * 2;
            const float* bsm = (const float*)(sm + SM_BIAS);
#pragma unroll
            for (int m2 = 0; m2 < 2; m2++) {
                const size_t mrow = (size_t)mt * 128 + msub + m2 * 16 + g;
                float* r0 = g_G + ((size_t)dir * BT_ + mrow) * NG_;
                float* r1 = r0 + 8 * NG_;
#pragma unroll
                for (int j = 0; j < 8; j++) {
                    const int col = nsub0 + 8 * j + t2;
                    float2 bv = *(const float2*)(bsm + col);
                    *(float2*)(r0 + col) =
                        make_float2(acc[m2][j][0] + bv.x, acc[m2][j][1] + bv.y);
                    *(float2*)(r1 + col) =
                        make_float2(acc[m2][j][2] + bv.x, acc[m2][j][3] + bv.y);
                }
            }
        }
    }
}

// =======================================================================
// Kernel 2: tensor-core recurrence.
// 64 CTAs = (2 dirs) x (32 chunks of 16 batches), 128 thr (4 warps).
// Whh as persistent mma B-fragments (f16, 64 regs/thread); per step:
// h (f16, smem) -> 4 ldsm A + 32 mma/warp -> gates; epilogue uses the
// mma fragment layout: lanes l, l^1 hold (i,g)/(f,o) of one h-unit ->
// R6 shfl.xor(1) exchange. c fp32 in regs (16/f-lane). xg via
// distance-2 cp.async triple buffer; ONE barrier per step.
// =======================================================================
__global__ void __launch_bounds__(128, 1) lstm_rec(
    const float* __restrict__ Whh_f, const float* __restrict__ Whh_b,
    float* __restrict__ out)
{
    extern __shared__ char sm2[];
    const uint32_t smb = smem_u32(sm2);

    const int tid  = threadIdx.x;
    const int wid  = tid >> 5;
    const int lane = tid & 31;
    const int dir  = blockIdx.x >> 5;
    const int b0   = (blockIdx.x & 31) << 4;

    const float* Whh = dir ? Whh_b : Whh_f;

    // ---- stage Whh f16 at permuted row p (slot map as g_G) ----
#pragma unroll
    for (int rr = 0; rr < 2; rr++) {
        const int j    = tid * 2 + rr;
        const int g    = j >> 6;
        const int slot = (g == 0) ? 0 : (g == 1) ? 2 : (g == 2) ? 1 : 3;
        const int p    = ((j & 63) << 2) | slot;
        const float4* wr = (const float4*)(Whh + j * 64);
        char* dst = sm2 + R_W + p * XSTRIDE;
#pragma unroll
        for (int q = 0; q < 16; q++) {
            float4 v = wr[q];
            *(uint2*)(dst + q * 8) = make_uint2(cvt2h(v.x, v.y), cvt2h(v.z, v.w));
        }
    }
    __syncthreads();

    // ---- persistent B fragments: warp covers p in [wid*64, wid*64+64) ----
    uint32_t Bf[4][4][4];
    {
        const uint32_t boff = (uint32_t)(wid * 64 + (lane & 7) + ((lane >> 4) << 3)) * XSTRIDE
                              + ((lane >> 3) & 1) * 16;
#pragma unroll
        for (int k8 = 0; k8 < 4; k8++)
#pragma unroll
            for (int jp = 0; jp < 4; jp++)
                ldsm4(Bf[k8][jp], smb + R_W + boff + jp * (16 * XSTRIDE) + k8 * 32);
    }

    // ---- zero h buffers (2 x 16 x 272 B = 2176 floats) ----
    for (int i = tid; i < 2176; i += 128)
        ((float*)(sm2 + R_H))[i] = 0.f;

    float cst[16];
#pragma unroll
    for (int u = 0; u < 16; u++) cst[u] = 0.f;

    const size_t xg_base = (size_t)dir * BT_ * NG_;

    // ---- prologue: prefetch xg for steps 0 and 1 ----
#pragma unroll
    for (int pf = 0; pf < 2; pf++) {
        const int tp = dir ? (T_ - 1 - pf) : pf;
        const uint32_t dst = smb + R_XG + pf * 16896;
#pragma unroll
        for (int i = 0; i < 8; i++) {
            const int chunk = tid + i * 128;
            const int row = chunk >> 6, p4 = chunk & 63;
            cp_async16(dst + row * 1056 + p4 * 16,
                       g_G + xg_base + ((size_t)(b0 + row) * T_ + tp) * NG_ + p4 * 4);
        }
        cp_commit();
    }
    cp_wait1();        // step-0 xg landed
    __syncthreads();   // visibility of xg + h zeros + W stage reuse ok

    // epilogue lane constants
    const int r    = lane >> 2;
    const int q4   = lane & 3;
    const int isB  = q4 & 1;
    const float s1 = isB ? 0.5f : 1.0f;   // val1: g -> tanh, o -> sigmoid
    const float m1 = isB ? 0.5f : 1.0f;
    const float k1 = isB ? 0.5f : 0.0f;
    const int hhb  = wid * 16 + (q4 >> 1);          // + b*2 per block
    float* outl = out + dir * 64 + hhb;

    const uint32_t aBase = smb + R_H + (uint32_t)(lane & 15) * XSTRIDE + (lane >> 4) * 16;

    int bufR = 0, bufW = 2;

    for (int s = 0; s < T_; s++) {
        const int t = dir ? (T_ - 1 - s) : s;

        // ---- prefetch xg for step s+2 ----
        if (s + 2 < T_) {
            const int tn = dir ? (T_ - 3 - s) : (s + 2);
            const uint32_t dst = smb + R_XG + bufW * 16896;
#pragma unroll
            for (int i = 0; i < 8; i++) {
                const int chunk = tid + i * 128;
                const int row = chunk >> 6, p4 = chunk & 63;
                cp_async16(dst + row * 1056 + p4 * 16,
                           g_G + xg_base + ((size_t)(b0 + row) * T_ + tn) * NG_ + p4 * 4);
            }
        }
        cp_commit();

        // ---- A fragments from h_s[cur] ----
        uint32_t A[4][4];
        const uint32_t aH = aBase + (s & 1) * 4352;
#pragma unroll
        for (int k8 = 0; k8 < 4; k8++) ldsm4(A[k8], aH + k8 * 32);

        // ---- 32 mma ----
        float acc[8][4];
#pragma unroll
        for (int q = 0; q < 8; q++)
#pragma unroll
            for (int e = 0; e < 4; e++) acc[q][e] = 0.f;
#pragma unroll
        for (int k8 = 0; k8 < 4; k8++)
#pragma unroll
            for (int jp = 0; jp < 4; jp++) {
                mma16816(acc[2 * jp + 0], A[k8], Bf[k8][jp][0], Bf[k8][jp][1]);
                mma16816(acc[2 * jp + 1], A[k8], Bf[k8][jp][2], Bf[k8][jp][3]);
            }

        // ---- epilogue ----
        const char* xgb = sm2 + R_XG + bufR * 16896;
        char* hnxt = sm2 + R_H + ((s & 1) ^ 1) * 4352;
        const size_t ob0 = ((size_t)(b0 + r) * T_ + t) * 128;
        const size_t ob1 = ((size_t)(b0 + r + 8) * T_ + t) * 128;

#pragma unroll
        for (int b = 0; b < 8; b++) {
            const int p0 = wid * 64 + b * 8 + q4 * 2;
#pragma unroll
            for (int rh = 0; rh < 2; rh++) {
                const int row = r + rh * 8;
                const float2 xg = *(const float2*)(xgb + row * 1056 + p0 * 4);
                const float v0 = acc[b][rh * 2 + 0] + xg.x;   // i or f
                const float v1 = acc[b][rh * 2 + 1] + xg.y;   // g or o

                const float t0 = sig_fast(v0);
                const float t1 = fmaf(tanh_fast(v1 * s1), m1, k1);

                const float v  = t0 * t1;                     // A: sig(i)*tanh(g)
                const float vr = __shfl_xor_sync(0xFFFFFFFFu, v, 1);

                const int u = b * 2 + rh;
                cst[u] = fmaf(t0, cst[u], vr);                // valid on B lanes
                const float h = t1 * tanh_fast(cst[u]);       // sig(o)*tanh(c)

                if (isB) {
                    *(__half*)(hnxt + row * 272 + (hhb + b * 2) * 2) = __float2half(h);
                    outl[(rh ? ob1 : ob0) + b * 2] = h;
                }
            }
        }

        cp_wait1();        // step s+1's xg group landed
        __syncthreads();   // h_s handoff + xg cross-thread visibility

        bufR = (bufR == 2) ? 0 : bufR + 1;
        bufW = (bufW == 2) ? 0 : bufW + 1;
    }
}

// =======================================================================
extern "C" void kernel_launch(void* const* d_in, const int* in_sizes, int n_in,
                              void* d_out, int out_size)
{
    const float* x    = (const float*)d_in[0];
    const float* Wihf = (const float*)d_in[1];
    const float* Whhf = (const float*)d_in[2];
    const float* bf   = (const float*)d_in[3];
    const float* Wihb = (const float*)d_in[4];
    const float* Whhb = (const float*)d_in[5];
    const float* bb   = (const float*)d_in[6];
    float* out = (float*)d_out;

    cudaFuncSetAttribute(gates_gemm, cudaFuncAttributeMaxDynamicSharedMemorySize, SM_TOTAL);
    cudaFuncSetAttribute(lstm_rec, cudaFuncAttributeMaxDynamicSharedMemorySize, R_TOT);

    gates_gemm<<<148, 512, SM_TOTAL>>>(x, Wihf, bf, Wihb, bb);
    lstm_rec<<<64, 128, R_TOT>>>(Whhf, Whhb, out);
}

// round 15
// speedup vs baseline: 1.3857x; 1.3857x over previous
#include <cuda_runtime.h>
#include <cuda_fp16.h>
#include <cstdint>

#define B_  512
#define T_  1024
#define IN_ 128
#define NG_ 256
#define BT_ (B_ * T_)
#define MTILES 4096          // BT_/128 m-tiles per dir

// xg scratch: [dir][b*T+t][hh*4 + slot], slot: 0=i,1=g,2=f,3=o  (1 GiB)
__device__ float g_G[(size_t)2 * BT_ * NG_];

// ---------------- smem map (bytes) for gates_gemm ----------------
#define XSTRIDE 272
#define SM_XH   0
#define SM_WHI  (SM_XH + 128 * XSTRIDE)      //  34816
#define SM_BIAS (SM_WHI + 256 * XSTRIDE)     // 104448
#define SM_TOTAL (SM_BIAS + 1024)            // 105472

// ---------------- smem map (bytes) for lstm_rec ----------------
#define R_W   0
#define R_H   69632
#define R_XG  (R_H + 2 * 16 * 272)           // 78336
#define R_TOT (R_XG + 3 * 16896)             // 129024

// ---------------- ptx helpers ----------------
__device__ __forceinline__ uint32_t smem_u32(const void* p) {
    return (uint32_t)__cvta_generic_to_shared(p);
}
__device__ __forceinline__ void ldsm4(uint32_t* r, uint32_t addr) {
    asm volatile("ldmatrix.sync.aligned.m8n8.x4.shared.b16 {%0,%1,%2,%3}, [%4];"
                 : "=r"(r[0]), "=r"(r[1]), "=r"(r[2]), "=r"(r[3]) : "r"(addr));
}
__device__ __forceinline__ void mma16816(float* c, const uint32_t* a,
                                         uint32_t b0, uint32_t b1) {
    asm volatile(
        "mma.sync.aligned.m16n8k16.row.col.f32.f16.f16.f32 "
        "{%0,%1,%2,%3}, {%4,%5,%6,%7}, {%8,%9}, {%0,%1,%2,%3};"
        : "+f"(c[0]), "+f"(c[1]), "+f"(c[2]), "+f"(c[3])
        : "r"(a[0]), "r"(a[1]), "r"(a[2]), "r"(a[3]), "r"(b0), "r"(b1));
}

// fp16x2 pack of two floats (lo half = a, hi half = b)
__device__ __forceinline__ uint32_t cvt2h(float a, float b) {
    __half2 h = __floats2half2_rn(a, b);
    return *reinterpret_cast<uint32_t*>(&h);
}

// ---------------- activations (MUFU tanh) ----------------
__device__ __forceinline__ float tanh_fast(float x) {
    float y;
    asm("tanh.approx.f32 %0, %1;" : "=f"(y) : "f"(x));
    return y;
}
__device__ __forceinline__ float sig_fast(float x) {
    return fmaf(tanh_fast(0.5f * x), 0.5f, 0.5f);
}

// ---------------- cp.async ----------------
__device__ __forceinline__ void cp_async16(uint32_t dst, const void* src) {
    asm volatile("cp.async.cg.shared.global [%0], [%1], 16;" :: "r"(dst), "l"(src));
}
__device__ __forceinline__ void cp_commit() {
    asm volatile("cp.async.commit_group;");
}
__device__ __forceinline__ void cp_wait1() {
    asm volatile("cp.async.wait_group 1;");
}

// =======================================================================
// Kernel 1: HMMA pure-fp16 GEMM (R13 winner, unchanged).
// =======================================================================
__global__ void __launch_bounds__(512, 1) gates_gemm(
    const float* __restrict__ x,
    const float* __restrict__ Wf, const float* __restrict__ bf,
    const float* __restrict__ Wb, const float* __restrict__ bb)
{
    extern __shared__ char sm[];
    const uint32_t smb = smem_u32(sm);

    const int tid  = threadIdx.x;
    const int wid  = tid >> 5;
    const int lane = tid & 31;
    const int dir  = blockIdx.x & 1;
    const int cpos = blockIdx.x >> 1;   // 0..73

    const float* W    = dir ? Wb : Wf;
    const float* bias = dir ? bb : bf;

    {
        const int j    = tid >> 1;
        const int half = tid & 1;
        const int g    = j >> 6;
        const int slot = (g == 0) ? 0 : (g == 1) ? 2 : (g == 2) ? 1 : 3;
        const int p    = ((j & 63) << 2) | slot;
        const float4* wr = (const float4*)(W + j * IN_ + half * 64);
        char* whi = sm + SM_WHI + p * XSTRIDE + half * 128;
#pragma unroll
        for (int q = 0; q < 16; q++) {
            float4 v = wr[q];
            *(uint2*)(whi + q * 8) = make_uint2(cvt2h(v.x, v.y), cvt2h(v.z, v.w));
        }
        if (half == 0) ((float*)(sm + SM_BIAS))[p] = bias[j];
    }

    const int msub  = (wid & 3) * 32;
    const int nsub0 = (wid >> 2) * 64;

    const uint32_t aoff = (uint32_t)(msub + (lane & 15)) * XSTRIDE + (lane >> 4) * 16;
    const uint32_t boff = (uint32_t)(nsub0 + (lane & 7) + ((lane >> 4) << 3)) * XSTRIDE
                          + ((lane >> 3) & 1) * 16;

    const int r0c = tid >> 5;
    const int lc  = tid & 31;

    for (int mt = cpos; mt < MTILES; mt += 74) {
        __syncthreads();

        {
            const float* srcb = x + (size_t)mt * 128 * IN_;
#pragma unroll
            for (int i = 0; i < 4; i++) {
                const int row0 = r0c + 32 * i;
                float4 v0 = *(const float4*)(srcb + (size_t)row0 * IN_ + lc * 4);
                float4 v1 = *(const float4*)(srcb + (size_t)(row0 + 16) * IN_ + lc * 4);
                *(uint2*)(sm + SM_XH + row0 * XSTRIDE + lc * 8) =
                    make_uint2(cvt2h(v0.x, v0.y), cvt2h(v0.z, v0.w));
                *(uint2*)(sm + SM_XH + (row0 + 16) * XSTRIDE + lc * 8) =
                    make_uint2(cvt2h(v1.x, v1.y), cvt2h(v1.z, v1.w));
            }
        }
        __syncthreads();

        float acc[2][8][4];
#pragma unroll
        for (int m2 = 0; m2 < 2; m2++)
#pragma unroll
            for (int j = 0; j < 8; j++)
#pragma unroll
                for (int q = 0; q < 4; q++) acc[m2][j][q] = 0.f;

        const uint32_t aH  = smb + SM_XH + aoff;
        const uint32_t bHi = smb + SM_WHI + boff;

#pragma unroll
        for (int k8 = 0; k8 < 8; k8++) {
            uint32_t ah0[4], ah1[4];
            ldsm4(ah0, aH + k8 * 32);
            ldsm4(ah1, aH + 16 * XSTRIDE + k8 * 32);
#pragma unroll
            for (int jp = 0; jp < 4; jp++) {
                uint32_t bh[4];
                ldsm4(bh, bHi + jp * (16 * XSTRIDE) + k8 * 32);
                mma16816(acc[0][2 * jp + 0], ah0, bh[0], bh[1]);
                mma16816(acc[0][2 * jp + 1], ah0, bh[2], bh[3]);
                mma16816(acc[1][2 * jp + 0], ah1, bh[0], bh[1]);
                mma16816(acc[1][2 * jp + 1], ah1, bh[2], bh[3]);
            }
        }

        {
            const int g  = lane >> 2;
            const int t2 = (lane & 3) * 2;
            const float* bsm = (const float*)(sm + SM_BIAS);
#pragma unroll
            for (int m2 = 0; m2 < 2; m2++) {
                const size_t mrow = (size_t)mt * 128 + msub + m2 * 16 + g;
                float* r0 = g_G + ((size_t)dir * BT_ + mrow) * NG_;
                float* r1 = r0 + 8 * NG_;
#pragma unroll
                for (int j = 0; j < 8; j++) {
                    const int col = nsub0 + 8 * j + t2;
                    float2 bv = *(const float2*)(bsm + col);
                    *(float2*)(r0 + col) =
                        make_float2(acc[m2][j][0] + bv.x, acc[m2][j][1] + bv.y);
                    *(float2*)(r1 + col) =
                        make_float2(acc[m2][j][2] + bv.x, acc[m2][j][3] + bv.y);
                }
            }
        }
    }
}

// =======================================================================
// Kernel 2: tensor-core recurrence, 8 warps (R14 structure, 2x warps).
// 64 CTAs = (2 dirs) x (32 chunks of 16 batches), 256 thr (8 warps,
// 2/SMSP). Warp owns 32 gate-cols: 16 mma/step, epilogue 8 units/lane
// (halved serial MUFU/shfl chain vs R14). Whh persistent B-fragments
// (32 regs). xg distance-2 cp.async triple buffer; ONE barrier/step.
// =======================================================================
__global__ void __launch_bounds__(256, 1) lstm_rec(
    const float* __restrict__ Whh_f, const float* __restrict__ Whh_b,
    float* __restrict__ out)
{
    extern __shared__ char sm2[];
    const uint32_t smb = smem_u32(sm2);

    const int tid  = threadIdx.x;
    const int wid  = tid >> 5;
    const int lane = tid & 31;
    const int dir  = blockIdx.x >> 5;
    const int b0   = (blockIdx.x & 31) << 4;

    const float* Whh = dir ? Whh_b : Whh_f;

    // ---- stage Whh f16 at permuted row p (slot map as g_G) ----
    {
        const int j    = tid;
        const int g    = j >> 6;
        const int slot = (g == 0) ? 0 : (g == 1) ? 2 : (g == 2) ? 1 : 3;
        const int p    = ((j & 63) << 2) | slot;
        const float4* wr = (const float4*)(Whh + j * 64);
        char* dst = sm2 + R_W + p * XSTRIDE;
#pragma unroll
        for (int q = 0; q < 16; q++) {
            float4 v = wr[q];
            *(uint2*)(dst + q * 8) = make_uint2(cvt2h(v.x, v.y), cvt2h(v.z, v.w));
        }
    }
    __syncthreads();

    // ---- persistent B fragments: warp covers p in [wid*32, wid*32+32) ----
    uint32_t Bf[4][2][4];
    {
        const uint32_t boff = (uint32_t)(wid * 32 + (lane & 7) + ((lane >> 4) << 3)) * XSTRIDE
                              + ((lane >> 3) & 1) * 16;
#pragma unroll
        for (int k8 = 0; k8 < 4; k8++)
#pragma unroll
            for (int jp = 0; jp < 2; jp++)
                ldsm4(Bf[k8][jp], smb + R_W + boff + jp * (16 * XSTRIDE) + k8 * 32);
    }

    // ---- zero h buffers (2 x 16 x 272 B = 2176 floats) ----
    for (int i = tid; i < 2176; i += 256)
        ((float*)(sm2 + R_H))[i] = 0.f;

    float cst[8];
#pragma unroll
    for (int u = 0; u < 8; u++) cst[u] = 0.f;

    const size_t xg_base = (size_t)dir * BT_ * NG_;

    // ---- prologue: prefetch xg for steps 0 and 1 ----
#pragma unroll
    for (int pf = 0; pf < 2; pf++) {
        const int tp = dir ? (T_ - 1 - pf) : pf;
        const uint32_t dst = smb + R_XG + pf * 16896;
#pragma unroll
        for (int i = 0; i < 4; i++) {
            const int chunk = tid + i * 256;
            const int row = chunk >> 6, p4 = chunk & 63;
            cp_async16(dst + row * 1056 + p4 * 16,
                       g_G + xg_base + ((size_t)(b0 + row) * T_ + tp) * NG_ + p4 * 4);
        }
        cp_commit();
    }
    cp_wait1();        // step-0 xg landed
    __syncthreads();

    // epilogue lane constants
    const int r    = lane >> 2;
    const int q4   = lane & 3;
    const int isB  = q4 & 1;
    const float s1 = isB ? 0.5f : 1.0f;   // val1: g -> tanh, o -> sigmoid
    const float m1 = isB ? 0.5f : 1.0f;
    const float k1 = isB ? 0.5f : 0.0f;
    const int hhb  = wid * 8 + (q4 >> 1);           // + b*2 per block
    float* outl = out + dir * 64 + hhb;

    const uint32_t aBase = smb + R_H + (uint32_t)(lane & 15) * XSTRIDE + (lane >> 4) * 16;

    int bufR = 0, bufW = 2;

    for (int s = 0; s < T_; s++) {
        const int t = dir ? (T_ - 1 - s) : s;

        // ---- prefetch xg for step s+2 ----
        if (s + 2 < T_) {
            const int tn = dir ? (T_ - 3 - s) : (s + 2);
            const uint32_t dst = smb + R_XG + bufW * 16896;
#pragma unroll
            for (int i = 0; i < 4; i++) {
                const int chunk = tid + i * 256;
                const int row = chunk >> 6, p4 = chunk & 63;
                cp_async16(dst + row * 1056 + p4 * 16,
                           g_G + xg_base + ((size_t)(b0 + row) * T_ + tn) * NG_ + p4 * 4);
            }
        }
        cp_commit();

        // ---- A fragments from h_s[cur] (broadcast across warps) ----
        uint32_t A[4][4];
        const uint32_t aH = aBase + (s & 1) * 4352;
#pragma unroll
        for (int k8 = 0; k8 < 4; k8++) ldsm4(A[k8], aH + k8 * 32);

        // ---- 16 mma ----
        float acc[4][4];
#pragma unroll
        for (int q = 0; q < 4; q++)
#pragma unroll
            for (int e = 0; e < 4; e++) acc[q][e] = 0.f;
#pragma unroll
        for (int k8 = 0; k8 < 4; k8++)
#pragma unroll
            for (int jp = 0; jp < 2; jp++) {
                mma16816(acc[2 * jp + 0], A[k8], Bf[k8][jp][0], Bf[k8][jp][1]);
                mma16816(acc[2 * jp + 1], A[k8], Bf[k8][jp][2], Bf[k8][jp][3]);
            }

        // ---- epilogue: 4 n8-blocks x 2 row-halves = 8 units/lane ----
        const char* xgb = sm2 + R_XG + bufR * 16896;
        char* hnxt = sm2 + R_H + ((s & 1) ^ 1) * 4352;
        const size_t ob0 = ((size_t)(b0 + r) * T_ + t) * 128;
        const size_t ob1 = ((size_t)(b0 + r + 8) * T_ + t) * 128;

#pragma unroll
        for (int b = 0; b < 4; b++) {
            const int p0 = wid * 32 + b * 8 + q4 * 2;
#pragma unroll
            for (int rh = 0; rh < 2; rh++) {
                const int row = r + rh * 8;
                const float2 xg = *(const float2*)(xgb + row * 1056 + p0 * 4);
                const float v0 = acc[b][rh * 2 + 0] + xg.x;   // i or f
                const float v1 = acc[b][rh * 2 + 1] + xg.y;   // g or o

                const float t0 = sig_fast(v0);
                const float t1 = fmaf(tanh_fast(v1 * s1), m1, k1);

                const float v  = t0 * t1;                     // A: sig(i)*tanh(g)
                const float vr = __shfl_xor_sync(0xFFFFFFFFu, v, 1);

                const int u = b * 2 + rh;
                cst[u] = fmaf(t0, cst[u], vr);                // valid on B lanes
                const float h = t1 * tanh_fast(cst[u]);       // sig(o)*tanh(c)

                if (isB) {
                    *(__half*)(hnxt + row * 272 + (hhb + b * 2) * 2) = __float2half(h);
                    outl[(rh ? ob1 : ob0) + b * 2] = h;
                }
            }
        }

        cp_wait1();        // step s+1's xg group landed
        __syncthreads();   // h_s handoff + xg cross-thread visibility

        bufR = (bufR == 2) ? 0 : bufR + 1;
        bufW = (bufW == 2) ? 0 : bufW + 1;
    }
}

// =======================================================================
extern "C" void kernel_launch(void* const* d_in, const int* in_sizes, int n_in,
                              void* d_out, int out_size)
{
    const float* x    = (const float*)d_in[0];
    const float* Wihf = (const float*)d_in[1];
    const float* Whhf = (const float*)d_in[2];
    const float* bf   = (const float*)d_in[3];
    const float* Wihb = (const float*)d_in[4];
    const float* Whhb = (const float*)d_in[5];
    const float* bb   = (const float*)d_in[6];
    float* out = (float*)d_out;

    cudaFuncSetAttribute(gates_gemm, cudaFuncAttributeMaxDynamicSharedMemorySize, SM_TOTAL);
    cudaFuncSetAttribute(lstm_rec, cudaFuncAttributeMaxDynamicSharedMemorySize, R_TOT);

    gates_gemm<<<148, 512, SM_TOTAL>>>(x, Wihf, bf, Wihb, bb);
    lstm_rec<<<64, 256, R_TOT>>>(Whhf, Whhb, out);
}

// round 16
// speedup vs baseline: 1.7474x; 1.2610x over previous
#include <cuda_runtime.h>
#include <cuda_fp16.h>
#include <cstdint>

#define B_  512
#define T_  1024
#define IN_ 128
#define NG_ 256
#define BT_ (B_ * T_)
#define MTILES 4096          // BT_/128 m-tiles per dir

// xg scratch: [dir][b*T+t][hh*4 + slot], slot: 0=i,1=g,2=f,3=o  (1 GiB)
__device__ float g_G[(size_t)2 * BT_ * NG_];

// ---------------- smem map (bytes) for gates_gemm ----------------
#define XSTRIDE 272
#define SM_XH   0
#define SM_WHI  (SM_XH + 128 * XSTRIDE)      //  34816
#define SM_BIAS (SM_WHI + 256 * XSTRIDE)     // 104448
#define SM_TOTAL (SM_BIAS + 1024)            // 105472

// ---------------- smem map (bytes) for lstm_rec ----------------
#define R_W   0
#define R_H   69632
#define R_XG  (R_H + 2 * 16 * 272)           // 78336
#define R_TOT (R_XG + 3 * 16896)             // 129024

// ---------------- ptx helpers ----------------
__device__ __forceinline__ uint32_t smem_u32(const void* p) {
    return (uint32_t)__cvta_generic_to_shared(p);
}
__device__ __forceinline__ void ldsm4(uint32_t* r, uint32_t addr) {
    asm volatile("ldmatrix.sync.aligned.m8n8.x4.shared.b16 {%0,%1,%2,%3}, [%4];"
                 : "=r"(r[0]), "=r"(r[1]), "=r"(r[2]), "=r"(r[3]) : "r"(addr));
}
__device__ __forceinline__ void mma16816(float* c, const uint32_t* a,
                                         uint32_t b0, uint32_t b1) {
    asm volatile(
        "mma.sync.aligned.m16n8k16.row.col.f32.f16.f16.f32 "
        "{%0,%1,%2,%3}, {%4,%5,%6,%7}, {%8,%9}, {%0,%1,%2,%3};"
        : "+f"(c[0]), "+f"(c[1]), "+f"(c[2]), "+f"(c[3])
        : "r"(a[0]), "r"(a[1]), "r"(a[2]), "r"(a[3]), "r"(b0), "r"(b1));
}

// fp16x2 pack of two floats (lo half = a, hi half = b)
__device__ __forceinline__ uint32_t cvt2h(float a, float b) {
    __half2 h = __floats2half2_rn(a, b);
    return *reinterpret_cast<uint32_t*>(&h);
}

// ---------------- activations (MUFU tanh) ----------------
__device__ __forceinline__ float tanh_fast(float x) {
    float y;
    asm("tanh.approx.f32 %0, %1;" : "=f"(y) : "f"(x));
    return y;
}
__device__ __forceinline__ float sig_fast(float x) {
    return fmaf(tanh_fast(0.5f * x), 0.5f, 0.5f);
}

// ---------------- cp.async ----------------
__device__ __forceinline__ void cp_async16(uint32_t dst, const void* src) {
    asm volatile("cp.async.cg.shared.global [%0], [%1], 16;" :: "r"(dst), "l"(src));
}
__device__ __forceinline__ void cp_commit() {
    asm volatile("cp.async.commit_group;");
}
__device__ __forceinline__ void cp_wait1() {
    asm volatile("cp.async.wait_group 1;");
}

// =======================================================================
// Kernel 1: HMMA pure-fp16 GEMM (R13 winner, unchanged).
// =======================================================================
__global__ void __launch_bounds__(512, 1) gates_gemm(
    const float* __restrict__ x,
    const float* __restrict__ Wf, const float* __restrict__ bf,
    const float* __restrict__ Wb, const float* __restrict__ bb)
{
    extern __shared__ char sm[];
    const uint32_t smb = smem_u32(sm);

    const int tid  = threadIdx.x;
    const int wid  = tid >> 5;
    const int lane = tid & 31;
    const int dir  = blockIdx.x & 1;
    const int cpos = blockIdx.x >> 1;   // 0..73

    const float* W    = dir ? Wb : Wf;
    const float* bias = dir ? bb : bf;

    {
        const int j    = tid >> 1;
        const int half = tid & 1;
        const int g    = j >> 6;
        const int slot = (g == 0) ? 0 : (g == 1) ? 2 : (g == 2) ? 1 : 3;
        const int p    = ((j & 63) << 2) | slot;
        const float4* wr = (const float4*)(W + j * IN_ + half * 64);
        char* whi = sm + SM_WHI + p * XSTRIDE + half * 128;
#pragma unroll
        for (int q = 0; q < 16; q++) {
            float4 v = wr[q];
            *(uint2*)(whi + q * 8) = make_uint2(cvt2h(v.x, v.y), cvt2h(v.z, v.w));
        }
        if (half == 0) ((float*)(sm + SM_BIAS))[p] = bias[j];
    }

    const int msub  = (wid & 3) * 32;
    const int nsub0 = (wid >> 2) * 64;

    const uint32_t aoff = (uint32_t)(msub + (lane & 15)) * XSTRIDE + (lane >> 4) * 16;
    const uint32_t boff = (uint32_t)(nsub0 + (lane & 7) + ((lane >> 4) << 3)) * XSTRIDE
                          + ((lane >> 3) & 1) * 16;

    const int r0c = tid >> 5;
    const int lc  = tid & 31;

    for (int mt = cpos; mt < MTILES; mt += 74) {
        __syncthreads();

        {
            const float* srcb = x + (size_t)mt * 128 * IN_;
#pragma unroll
            for (int i = 0; i < 4; i++) {
                const int row0 = r0c + 32 * i;
                float4 v0 = *(const float4*)(srcb + (size_t)row0 * IN_ + lc * 4);
                float4 v1 = *(const float4*)(srcb + (size_t)(row0 + 16) * IN_ + lc * 4);
                *(uint2*)(sm + SM_XH + row0 * XSTRIDE + lc * 8) =
                    make_uint2(cvt2h(v0.x, v0.y), cvt2h(v0.z, v0.w));
                *(uint2*)(sm + SM_XH + (row0 + 16) * XSTRIDE + lc * 8) =
                    make_uint2(cvt2h(v1.x, v1.y), cvt2h(v1.z, v1.w));
            }
        }
        __syncthreads();

        float acc[2][8][4];
#pragma unroll
        for (int m2 = 0; m2 < 2; m2++)
#pragma unroll
            for (int j = 0; j < 8; j++)
#pragma unroll
                for (int q = 0; q < 4; q++) acc[m2][j][q] = 0.f;

        const uint32_t aH  = smb + SM_XH + aoff;
        const uint32_t bHi = smb + SM_WHI + boff;

#pragma unroll
        for (int k8 = 0; k8 < 8; k8++) {
            uint32_t ah0[4], ah1[4];
            ldsm4(ah0, aH + k8 * 32);
            ldsm4(ah1, aH + 16 * XSTRIDE + k8 * 32);
#pragma unroll
            for (int jp = 0; jp < 4; jp++) {
                uint32_t bh[4];
                ldsm4(bh, bHi + jp * (16 * XSTRIDE) + k8 * 32);
                mma16816(acc[0][2 * jp + 0], ah0, bh[0], bh[1]);
                mma16816(acc[0][2 * jp + 1], ah0, bh[2], bh[3]);
                mma16816(acc[1][2 * jp + 0], ah1, bh[0], bh[1]);
                mma16816(acc[1][2 * jp + 1], ah1, bh[2], bh[3]);
            }
        }

        {
            const int g  = lane >> 2;
            const int t2 = (lane & 3) * 2;
            const float* bsm = (const float*)(sm + SM_BIAS);
#pragma unroll
            for (int m2 = 0; m2 < 2; m2++) {
                const size_t mrow = (size_t)mt * 128 + msub + m2 * 16 + g;
                float* r0 = g_G + ((size_t)dir * BT_ + mrow) * NG_;
                float* r1 = r0 + 8 * NG_;
#pragma unroll
                for (int j = 0; j < 8; j++) {
                    const int col = nsub0 + 8 * j + t2;
                    float2 bv = *(const float2*)(bsm + col);
                    *(float2*)(r0 + col) =
                        make_float2(acc[m2][j][0] + bv.x, acc[m2][j][1] + bv.y);
                    *(float2*)(r1 + col) =
                        make_float2(acc[m2][j][2] + bv.x, acc[m2][j][3] + bv.y);
                }
            }
        }
    }
}

// =======================================================================
// Kernel 2: tensor-core recurrence, 16 warps (R15 structure, 2x warps).
// 64 CTAs = (2 dirs) x (32 chunks of 16 batches), 512 thr (16 warps,
// 4/SMSP). Warp owns 16 gate-cols: 8 mma/step, epilogue 4 units/lane
// (halved serial MUFU/shfl chain vs R15). Whh persistent B-fragments
// (16 regs). xg distance-2 cp.async triple buffer; ONE barrier/step.
// =======================================================================
__global__ void __launch_bounds__(512, 1) lstm_rec(
    const float* __restrict__ Whh_f, const float* __restrict__ Whh_b,
    float* __restrict__ out)
{
    extern __shared__ char sm2[];
    const uint32_t smb = smem_u32(sm2);

    const int tid  = threadIdx.x;
    const int wid  = tid >> 5;
    const int lane = tid & 31;
    const int dir  = blockIdx.x >> 5;
    const int b0   = (blockIdx.x & 31) << 4;

    const float* Whh = dir ? Whh_b : Whh_f;

    // ---- stage Whh f16 at permuted row p (slot map as g_G) ----
    if (tid < 256) {
        const int j    = tid;
        const int g    = j >> 6;
        const int slot = (g == 0) ? 0 : (g == 1) ? 2 : (g == 2) ? 1 : 3;
        const int p    = ((j & 63) << 2) | slot;
        const float4* wr = (const float4*)(Whh + j * 64);
        char* dst = sm2 + R_W + p * XSTRIDE;
#pragma unroll
        for (int q = 0; q < 16; q++) {
            float4 v = wr[q];
            *(uint2*)(dst + q * 8) = make_uint2(cvt2h(v.x, v.y), cvt2h(v.z, v.w));
        }
    }
    __syncthreads();

    // ---- persistent B fragments: warp covers p in [wid*16, wid*16+16) ----
    uint32_t Bf[4][4];
    {
        const uint32_t boff = (uint32_t)(wid * 16 + (lane & 7) + ((lane >> 4) << 3)) * XSTRIDE
                              + ((lane >> 3) & 1) * 16;
#pragma unroll
        for (int k8 = 0; k8 < 4; k8++)
            ldsm4(Bf[k8], smb + R_W + boff + k8 * 32);
    }

    // ---- zero h buffers (2 x 16 x 272 B = 2176 floats) ----
    for (int i = tid; i < 2176; i += 512)
        ((float*)(sm2 + R_H))[i] = 0.f;

    float cst[4];
#pragma unroll
    for (int u = 0; u < 4; u++) cst[u] = 0.f;

    const size_t xg_base = (size_t)dir * BT_ * NG_;

    // ---- prologue: prefetch xg for steps 0 and 1 ----
#pragma unroll
    for (int pf = 0; pf < 2; pf++) {
        const int tp = dir ? (T_ - 1 - pf) : pf;
        const uint32_t dst = smb + R_XG + pf * 16896;
#pragma unroll
        for (int i = 0; i < 2; i++) {
            const int chunk = tid + i * 512;
            const int row = chunk >> 6, p4 = chunk & 63;
            cp_async16(dst + row * 1056 + p4 * 16,
                       g_G + xg_base + ((size_t)(b0 + row) * T_ + tp) * NG_ + p4 * 4);
        }
        cp_commit();
    }
    cp_wait1();        // step-0 xg landed
    __syncthreads();

    // epilogue lane constants
    const int r    = lane >> 2;
    const int q4   = lane & 3;
    const int isB  = q4 & 1;
    const float s1 = isB ? 0.5f : 1.0f;   // val1: g -> tanh, o -> sigmoid
    const float m1 = isB ? 0.5f : 1.0f;
    const float k1 = isB ? 0.5f : 0.0f;
    const int hhb  = wid * 4 + (q4 >> 1);           // + b*2 per block
    float* outl = out + dir * 64 + hhb;

    const uint32_t aBase = smb + R_H + (uint32_t)(lane & 15) * XSTRIDE + (lane >> 4) * 16;

    int bufR = 0, bufW = 2;

    for (int s = 0; s < T_; s++) {
        const int t = dir ? (T_ - 1 - s) : s;

        // ---- prefetch xg for step s+2 ----
        if (s + 2 < T_) {
            const int tn = dir ? (T_ - 3 - s) : (s + 2);
            const uint32_t dst = smb + R_XG + bufW * 16896;
#pragma unroll
            for (int i = 0; i < 2; i++) {
                const int chunk = tid + i * 512;
                const int row = chunk >> 6, p4 = chunk & 63;
                cp_async16(dst + row * 1056 + p4 * 16,
                           g_G + xg_base + ((size_t)(b0 + row) * T_ + tn) * NG_ + p4 * 4);
            }
        }
        cp_commit();

        // ---- A fragments from h_s[cur] (broadcast across warps) ----
        uint32_t A[4][4];
        const uint32_t aH = aBase + (s & 1) * 4352;
#pragma unroll
        for (int k8 = 0; k8 < 4; k8++) ldsm4(A[k8], aH + k8 * 32);

        // ---- 8 mma ----
        float acc[2][4];
#pragma unroll
        for (int q = 0; q < 2; q++)
#pragma unroll
            for (int e = 0; e < 4; e++) acc[q][e] = 0.f;
#pragma unroll
        for (int k8 = 0; k8 < 4; k8++) {
            mma16816(acc[0], A[k8], Bf[k8][0], Bf[k8][1]);
            mma16816(acc[1], A[k8], Bf[k8][2], Bf[k8][3]);
        }

        // ---- epilogue: 2 n8-blocks x 2 row-halves = 4 units/lane ----
        const char* xgb = sm2 + R_XG + bufR * 16896;
        char* hnxt = sm2 + R_H + ((s & 1) ^ 1) * 4352;
        const size_t ob0 = ((size_t)(b0 + r) * T_ + t) * 128;
        const size_t ob1 = ((size_t)(b0 + r + 8) * T_ + t) * 128;

#pragma unroll
        for (int b = 0; b < 2; b++) {
            const int p0 = wid * 16 + b * 8 + q4 * 2;
#pragma unroll
            for (int rh = 0; rh < 2; rh++) {
                const int row = r + rh * 8;
                const float2 xg = *(const float2*)(xgb + row * 1056 + p0 * 4);
                const float v0 = acc[b][rh * 2 + 0] + xg.x;   // i or f
                const float v1 = acc[b][rh * 2 + 1] + xg.y;   // g or o

                const float t0 = sig_fast(v0);
                const float t1 = fmaf(tanh_fast(v1 * s1), m1, k1);

                const float v  = t0 * t1;                     // A: sig(i)*tanh(g)
                const float vr = __shfl_xor_sync(0xFFFFFFFFu, v, 1);

                const int u = b * 2 + rh;
                cst[u] = fmaf(t0, cst[u], vr);                // valid on B lanes
                const float h = t1 * tanh_fast(cst[u]);       // sig(o)*tanh(c)

                if (isB) {
                    *(__half*)(hnxt + row * 272 + (hhb + b * 2) * 2) = __float2half(h);
                    outl[(rh ? ob1 : ob0) + b * 2] = h;
                }
            }
        }

        cp_wait1();        // step s+1's xg group landed
        __syncthreads();   // h_s handoff + xg cross-thread visibility

        bufR = (bufR == 2) ? 0 : bufR + 1;
        bufW = (bufW == 2) ? 0 : bufW + 1;
    }
}

// =======================================================================
extern "C" void kernel_launch(void* const* d_in, const int* in_sizes, int n_in,
                              void* d_out, int out_size)
{
    const float* x    = (const float*)d_in[0];
    const float* Wihf = (const float*)d_in[1];
    const float* Whhf = (const float*)d_in[2];
    const float* bf   = (const float*)d_in[3];
    const float* Wihb = (const float*)d_in[4];
    const float* Whhb = (const float*)d_in[5];
    const float* bb   = (const float*)d_in[6];
    float* out = (float*)d_out;

    cudaFuncSetAttribute(gates_gemm, cudaFuncAttributeMaxDynamicSharedMemorySize, SM_TOTAL);
    cudaFuncSetAttribute(lstm_rec, cudaFuncAttributeMaxDynamicSharedMemorySize, R_TOT);

    gates_gemm<<<148, 512, SM_TOTAL>>>(x, Wihf, bf, Wihb, bb);
    lstm_rec<<<64, 512, R_TOT>>>(Whhf, Whhb, out);
}

// round 17
// speedup vs baseline: 2.2981x; 1.3151x over previous
#include <cuda_runtime.h>
#include <cuda_fp16.h>
#include <cstdint>

#define B_  512
#define T_  1024
#define IN_ 128
#define NG_ 256
#define BT_ (B_ * T_)
#define MTILES 4096          // BT_/128 m-tiles per dir

// xg scratch: [dir][b*T+t][hh*4 + slot], slot: 0=i,1=g,2=f,3=o  (1 GiB)
__device__ float g_G[(size_t)2 * BT_ * NG_];

// ---------------- smem map (bytes) for gates_gemm ----------------
#define XSTRIDE 272
#define SM_XH   0
#define SM_WHI  (SM_XH + 128 * XSTRIDE)      //  34816
#define SM_BIAS (SM_WHI + 256 * XSTRIDE)     // 104448
#define SM_TOTAL (SM_BIAS + 1024)            // 105472

// ---------------- smem map (bytes) for lstm_rec ----------------
// W stage: 256 x 272 B; h: 2 bufs x 16 rows x 272 B (rows 8-15 stay 0);
// xg: 3 bufs x 8 rows x 1056 B.
#define R_W   0
#define R_H   69632
#define R_XG  (R_H + 2 * 16 * 272)           // 78336
#define R_TOT (R_XG + 3 * 8448)              // 103680

// ---------------- ptx helpers ----------------
__device__ __forceinline__ uint32_t smem_u32(const void* p) {
    return (uint32_t)__cvta_generic_to_shared(p);
}
__device__ __forceinline__ void ldsm4(uint32_t* r, uint32_t addr) {
    asm volatile("ldmatrix.sync.aligned.m8n8.x4.shared.b16 {%0,%1,%2,%3}, [%4];"
                 : "=r"(r[0]), "=r"(r[1]), "=r"(r[2]), "=r"(r[3]) : "r"(addr));
}
__device__ __forceinline__ void mma16816(float* c, const uint32_t* a,
                                         uint32_t b0, uint32_t b1) {
    asm volatile(
        "mma.sync.aligned.m16n8k16.row.col.f32.f16.f16.f32 "
        "{%0,%1,%2,%3}, {%4,%5,%6,%7}, {%8,%9}, {%0,%1,%2,%3};"
        : "+f"(c[0]), "+f"(c[1]), "+f"(c[2]), "+f"(c[3])
        : "r"(a[0]), "r"(a[1]), "r"(a[2]), "r"(a[3]), "r"(b0), "r"(b1));
}

// fp16x2 pack of two floats (lo half = a, hi half = b)
__device__ __forceinline__ uint32_t cvt2h(float a, float b) {
    __half2 h = __floats2half2_rn(a, b);
    return *reinterpret_cast<uint32_t*>(&h);
}

// ---------------- activations (MUFU tanh) ----------------
__device__ __forceinline__ float tanh_fast(float x) {
    float y;
    asm("tanh.approx.f32 %0, %1;" : "=f"(y) : "f"(x));
    return y;
}
__device__ __forceinline__ float sig_fast(float x) {
    return fmaf(tanh_fast(0.5f * x), 0.5f, 0.5f);
}

// ---------------- cp.async ----------------
__device__ __forceinline__ void cp_async16(uint32_t dst, const void* src) {
    asm volatile("cp.async.cg.shared.global [%0], [%1], 16;" :: "r"(dst), "l"(src));
}
__device__ __forceinline__ void cp_commit() {
    asm volatile("cp.async.commit_group;");
}
__device__ __forceinline__ void cp_wait1() {
    asm volatile("cp.async.wait_group 1;");
}

// =======================================================================
// Kernel 1: HMMA pure-fp16 GEMM (R13 winner, unchanged).
// =======================================================================
__global__ void __launch_bounds__(512, 1) gates_gemm(
    const float* __restrict__ x,
    const float* __restrict__ Wf, const float* __restrict__ bf,
    const float* __restrict__ Wb, const float* __restrict__ bb)
{
    extern __shared__ char sm[];
    const uint32_t smb = smem_u32(sm);

    const int tid  = threadIdx.x;
    const int wid  = tid >> 5;
    const int lane = tid & 31;
    const int dir  = blockIdx.x & 1;
    const int cpos = blockIdx.x >> 1;   // 0..73

    const float* W    = dir ? Wb : Wf;
    const float* bias = dir ? bb : bf;

    {
        const int j    = tid >> 1;
        const int half = tid & 1;
        const int g    = j >> 6;
        const int slot = (g == 0) ? 0 : (g == 1) ? 2 : (g == 2) ? 1 : 3;
        const int p    = ((j & 63) << 2) | slot;
        const float4* wr = (const float4*)(W + j * IN_ + half * 64);
        char* whi = sm + SM_WHI + p * XSTRIDE + half * 128;
#pragma unroll
        for (int q = 0; q < 16; q++) {
            float4 v = wr[q];
            *(uint2*)(whi + q * 8) = make_uint2(cvt2h(v.x, v.y), cvt2h(v.z, v.w));
        }
        if (half == 0) ((float*)(sm + SM_BIAS))[p] = bias[j];
    }

    const int msub  = (wid & 3) * 32;
    const int nsub0 = (wid >> 2) * 64;

    const uint32_t aoff = (uint32_t)(msub + (lane & 15)) * XSTRIDE + (lane >> 4) * 16;
    const uint32_t boff = (uint32_t)(nsub0 + (lane & 7) + ((lane >> 4) << 3)) * XSTRIDE
                          + ((lane >> 3) & 1) * 16;

    const int r0c = tid >> 5;
    const int lc  = tid & 31;

    for (int mt = cpos; mt < MTILES; mt += 74) {
        __syncthreads();

        {
            const float* srcb = x + (size_t)mt * 128 * IN_;
#pragma unroll
            for (int i = 0; i < 4; i++) {
                const int row0 = r0c + 32 * i;
                float4 v0 = *(const float4*)(srcb + (size_t)row0 * IN_ + lc * 4);
                float4 v1 = *(const float4*)(srcb + (size_t)(row0 + 16) * IN_ + lc * 4);
                *(uint2*)(sm + SM_XH + row0 * XSTRIDE + lc * 8) =
                    make_uint2(cvt2h(v0.x, v0.y), cvt2h(v0.z, v0.w));
                *(uint2*)(sm + SM_XH + (row0 + 16) * XSTRIDE + lc * 8) =
                    make_uint2(cvt2h(v1.x, v1.y), cvt2h(v1.z, v1.w));
            }
        }
        __syncthreads();

        float acc[2][8][4];
#pragma unroll
        for (int m2 = 0; m2 < 2; m2++)
#pragma unroll
            for (int j = 0; j < 8; j++)
#pragma unroll
                for (int q = 0; q < 4; q++) acc[m2][j][q] = 0.f;

        const uint32_t aH  = smb + SM_XH + aoff;
        const uint32_t bHi = smb + SM_WHI + boff;

#pragma unroll
        for (int k8 = 0; k8 < 8; k8++) {
            uint32_t ah0[4], ah1[4];
            ldsm4(ah0, aH + k8 * 32);
            ldsm4(ah1, aH + 16 * XSTRIDE + k8 * 32);
#pragma unroll
            for (int jp = 0; jp < 4; jp++) {
                uint32_t bh[4];
                ldsm4(bh, bHi + jp * (16 * XSTRIDE) + k8 * 32);
                mma16816(acc[0][2 * jp + 0], ah0, bh[0], bh[1]);
                mma16816(acc[0][2 * jp + 1], ah0, bh[2], bh[3]);
                mma16816(acc[1][2 * jp + 0], ah1, bh[0], bh[1]);
                mma16816(acc[1][2 * jp + 1], ah1, bh[2], bh[3]);
            }
        }

        {
            const int g  = lane >> 2;
            const int t2 = (lane & 3) * 2;
            const float* bsm = (const float*)(sm + SM_BIAS);
#pragma unroll
            for (int m2 = 0; m2 < 2; m2++) {
                const size_t mrow = (size_t)mt * 128 + msub + m2 * 16 + g;
                float* r0 = g_G + ((size_t)dir * BT_ + mrow) * NG_;
                float* r1 = r0 + 8 * NG_;
#pragma unroll
                for (int j = 0; j < 8; j++) {
                    const int col = nsub0 + 8 * j + t2;
                    float2 bv = *(const float2*)(bsm + col);
                    *(float2*)(r0 + col) =
                        make_float2(acc[m2][j][0] + bv.x, acc[m2][j][1] + bv.y);
                    *(float2*)(r1 + col) =
                        make_float2(acc[m2][j][2] + bv.x, acc[m2][j][3] + bv.y);
                }
            }
        }
    }
}

// =======================================================================
// Kernel 2: tensor-core recurrence, 8-batch chunks (chain halved again).
// 128 CTAs = (2 dirs) x (64 chunks of 8 batches), 512 thr (16 warps).
// Warp owns 16 gate-cols: 8 mma/step (rows 8-15 dead, h rows 8-15
// zeroed), epilogue 2 units/lane. 128/148 SMs active.
// xg distance-2 cp.async triple buffer (8 rows); ONE barrier/step.
// =======================================================================
__global__ void __launch_bounds__(512, 1) lstm_rec(
    const float* __restrict__ Whh_f, const float* __restrict__ Whh_b,
    float* __restrict__ out)
{
    extern __shared__ char sm2[];
    const uint32_t smb = smem_u32(sm2);

    const int tid  = threadIdx.x;
    const int wid  = tid >> 5;
    const int lane = tid & 31;
    const int dir  = blockIdx.x >> 6;
    const int b0   = (blockIdx.x & 63) << 3;

    const float* Whh = dir ? Whh_b : Whh_f;

    // ---- stage Whh f16 at permuted row p (slot map as g_G) ----
    if (tid < 256) {
        const int j    = tid;
        const int g    = j >> 6;
        const int slot = (g == 0) ? 0 : (g == 1) ? 2 : (g == 2) ? 1 : 3;
        const int p    = ((j & 63) << 2) | slot;
        const float4* wr = (const float4*)(Whh + j * 64);
        char* dst = sm2 + R_W + p * XSTRIDE;
#pragma unroll
        for (int q = 0; q < 16; q++) {
            float4 v = wr[q];
            *(uint2*)(dst + q * 8) = make_uint2(cvt2h(v.x, v.y), cvt2h(v.z, v.w));
        }
    }
    __syncthreads();

    // ---- persistent B fragments: warp covers p in [wid*16, wid*16+16) ----
    uint32_t Bf[4][4];
    {
        const uint32_t boff = (uint32_t)(wid * 16 + (lane & 7) + ((lane >> 4) << 3)) * XSTRIDE
                              + ((lane >> 3) & 1) * 16;
#pragma unroll
        for (int k8 = 0; k8 < 4; k8++)
            ldsm4(Bf[k8], smb + R_W + boff + k8 * 32);
    }

    // ---- zero h buffers (2 x 16 x 272 B; rows 8-15 stay zero forever) ----
    for (int i = tid; i < 2176; i += 512)
        ((float*)(sm2 + R_H))[i] = 0.f;

    float cst[2] = {0.f, 0.f};

    const size_t xg_base = (size_t)dir * BT_ * NG_;

    // ---- prologue: prefetch xg for steps 0 and 1 (8 rows = 512 chunks) ----
#pragma unroll
    for (int pf = 0; pf < 2; pf++) {
        const int tp = dir ? (T_ - 1 - pf) : pf;
        const uint32_t dst = smb + R_XG + pf * 8448;
        const int row = tid >> 6, p4 = tid & 63;
        cp_async16(dst + row * 1056 + p4 * 16,
                   g_G + xg_base + ((size_t)(b0 + row) * T_ + tp) * NG_ + p4 * 4);
        cp_commit();
    }
    cp_wait1();        // step-0 xg landed
    __syncthreads();

    // epilogue lane constants
    const int r    = lane >> 2;           // batch row 0..7
    const int q4   = lane & 3;
    const int isB  = q4 & 1;
    const float s1 = isB ? 0.5f : 1.0f;   // val1: g -> tanh, o -> sigmoid
    const float m1 = isB ? 0.5f : 1.0f;
    const float k1 = isB ? 0.5f : 0.0f;
    const int hhb  = wid * 4 + (q4 >> 1);           // + b*2 per block
    float* outl = out + dir * 64 + hhb;

    const uint32_t aBase = smb + R_H + (uint32_t)(lane & 15) * XSTRIDE + (lane >> 4) * 16;

    int bufR = 0, bufW = 2;

    for (int s = 0; s < T_; s++) {
        const int t = dir ? (T_ - 1 - s) : s;

        // ---- prefetch xg for step s+2 ----
        if (s + 2 < T_) {
            const int tn = dir ? (T_ - 3 - s) : (s + 2);
            const uint32_t dst = smb + R_XG + bufW * 8448;
            const int row = tid >> 6, p4 = tid & 63;
            cp_async16(dst + row * 1056 + p4 * 16,
                       g_G + xg_base + ((size_t)(b0 + row) * T_ + tn) * NG_ + p4 * 4);
        }
        cp_commit();

        // ---- A fragments from h_s[cur] (rows 8-15 are zeros) ----
        uint32_t A[4][4];
        const uint32_t aH = aBase + (s & 1) * 4352;
#pragma unroll
        for (int k8 = 0; k8 < 4; k8++) ldsm4(A[k8], aH + k8 * 32);

        // ---- 8 mma ----
        float acc[2][4];
#pragma unroll
        for (int q = 0; q < 2; q++)
#pragma unroll
            for (int e = 0; e < 4; e++) acc[q][e] = 0.f;
#pragma unroll
        for (int k8 = 0; k8 < 4; k8++) {
            mma16816(acc[0], A[k8], Bf[k8][0], Bf[k8][1]);
            mma16816(acc[1], A[k8], Bf[k8][2], Bf[k8][3]);
        }

        // ---- epilogue: 2 n8-blocks x 1 row = 2 units/lane ----
        const char* xgb = sm2 + R_XG + bufR * 8448;
        char* hnxt = sm2 + R_H + ((s & 1) ^ 1) * 4352;
        const size_t ob0 = ((size_t)(b0 + r) * T_ + t) * 128;

#pragma unroll
        for (int b = 0; b < 2; b++) {
            const int p0 = wid * 16 + b * 8 + q4 * 2;
            const float2 xg = *(const float2*)(xgb + r * 1056 + p0 * 4);
            const float v0 = acc[b][0] + xg.x;   // i or f
            const float v1 = acc[b][1] + xg.y;   // g or o

            const float t0 = sig_fast(v0);
            const float t1 = fmaf(tanh_fast(v1 * s1), m1, k1);

            const float v  = t0 * t1;                     // A: sig(i)*tanh(g)
            const float vr = __shfl_xor_sync(0xFFFFFFFFu, v, 1);

            cst[b] = fmaf(t0, cst[b], vr);                // valid on B lanes
            const float h = t1 * tanh_fast(cst[b]);       // sig(o)*tanh(c)

            if (isB) {
                *(__half*)(hnxt + r * 272 + (hhb + b * 2) * 2) = __float2half(h);
                outl[ob0 + b * 2] = h;
            }
        }

        cp_wait1();        // step s+1's xg group landed
        __syncthreads();   // h_s handoff + xg cross-thread visibility

        bufR = (bufR == 2) ? 0 : bufR + 1;
        bufW = (bufW == 2) ? 0 : bufW + 1;
    }
}

// =======================================================================
extern "C" void kernel_launch(void* const* d_in, const int* in_sizes, int n_in,
                              void* d_out, int out_size)
{
    const float* x    = (const float*)d_in[0];
    const float* Wihf = (const float*)d_in[1];
    const float* Whhf = (const float*)d_in[2];
    const float* bf   = (const float*)d_in[3];
    const float* Wihb = (const float*)d_in[4];
    const float* Whhb = (const float*)d_in[5];
    const float* bb   = (const float*)d_in[6];
    float* out = (float*)d_out;

    cudaFuncSetAttribute(gates_gemm, cudaFuncAttributeMaxDynamicSharedMemorySize, SM_TOTAL);
    cudaFuncSetAttribute(lstm_rec, cudaFuncAttributeMaxDynamicSharedMemorySize, R_TOT);

    gates_gemm<<<148, 512, SM_TOTAL>>>(x, Wihf, bf, Wihb, bb);
    lstm_rec<<<128, 512, R_TOT>>>(Whhf, Whhb, out);
}